// round 8
// baseline (speedup 1.0000x reference)
#include <cuda_runtime.h>
#include <cuda_fp16.h>
#include <mma.h>

using namespace nvcuda;

#define NN 50000
#define NE 800000
#define FF 128
#define MQ 32                      // uint2 (4 halves) per fp16 row
#define NG 64
#define NC 16
#define SCAN_B 512
#define NBLK ((NN + SCAN_B - 1) / SCAN_B)   // 98

// GEMM tiling
#define BM 64
#define LDA 40                     // 32 + 8 skew
#define LDW 136                    // 128 + 8 skew
#define SMEM_FLOATS 8704           // max(64*40 + 32*136, 64*136)

// ---------------- scratch (static device globals; no allocation) ----------------
__device__ int    g_is64;
__device__ int    g_counts[NN];
__device__ int    g_fill[NN];
__device__ int    g_rowptr[NN + 1];
__device__ int    g_col[NE];
__device__ float  g_dinv[NN];
__device__ uint2  g_msg[NN * MQ];    // fp16 messages (dinv-scaled GEMM output)
__device__ uint2  g_act[NN * MQ];    // fp16 activations (agg output, layer input)
__device__ float  g_pool[NG * FF];
__device__ int    g_bsum[NBLK];

// bit reinterpretation helpers
__device__ __forceinline__ unsigned h2u(__half2 h) { return *reinterpret_cast<unsigned*>(&h); }
__device__ __forceinline__ __half2 u2h(unsigned u) { return *reinterpret_cast<__half2*>(&u); }

// dtype-agnostic index load (edge_index / batch may be int32 or int64)
__device__ __forceinline__ int load_idx(const void* p, long long i, int is64) {
    if (is64) return (int)((const long long*)p)[i];
    return ((const int*)p)[i];
}

// ---------------- init: zero counts + dtype detect ----------------
__global__ void k_init(const int* __restrict__ w32) {
    int i = blockIdx.x * blockDim.x + threadIdx.x;
    if (i < NN) { g_counts[i] = 0; g_fill[i] = 0; }
    if (i == 0) {
        int nz = 0;
        #pragma unroll
        for (int k = 0; k < 16; k++) nz |= w32[2 * k + 1];
        g_is64 = (nz == 0) ? 1 : 0;
    }
}

__global__ void k_count(const void* __restrict__ ei) {
    int i = blockIdx.x * blockDim.x + threadIdx.x;
    if (i >= NE) return;
    int d = load_idx(ei, (long long)NE + i, g_is64);
    atomicAdd(&g_counts[d], 1);
}

// block-wide inclusive scan via shuffles; writes exclusive partials + block sums
__global__ void k_scan1() {
    __shared__ int warp_sums[SCAN_B / 32];
    int i = blockIdx.x * SCAN_B + threadIdx.x;
    int v = (i < NN) ? g_counts[i] : 0;
    int lane = threadIdx.x & 31;
    int wid  = threadIdx.x >> 5;

    int x = v;
    #pragma unroll
    for (int off = 1; off < 32; off <<= 1) {
        int t = __shfl_up_sync(0xffffffffu, x, off);
        if (lane >= off) x += t;
    }
    if (lane == 31) warp_sums[wid] = x;
    __syncthreads();
    if (wid == 0) {
        int w = (lane < SCAN_B / 32) ? warp_sums[lane] : 0;
        #pragma unroll
        for (int off = 1; off < SCAN_B / 32; off <<= 1) {
            int t = __shfl_up_sync(0xffffffffu, w, off);
            if (lane >= off) w += t;
        }
        if (lane < SCAN_B / 32) warp_sums[lane] = w;
    }
    __syncthreads();
    int base = (wid > 0) ? warp_sums[wid - 1] : 0;
    int incl = base + x;
    if (i < NN) g_rowptr[i] = incl - v;            // exclusive within block
    if (threadIdx.x == SCAN_B - 1) g_bsum[blockIdx.x] = incl;
}

// finalize rowptr: block b adds sum(bsum[0..b-1]); also compute dinv
__global__ void k_scan3() {
    __shared__ int s_off;
    int b = blockIdx.x;
    if (threadIdx.x < 32) {
        int acc = 0;
        for (int k = threadIdx.x; k < b; k += 32) acc += g_bsum[k];
        #pragma unroll
        for (int off = 16; off; off >>= 1) acc += __shfl_down_sync(0xffffffffu, acc, off);
        if (threadIdx.x == 0) s_off = acc;
    }
    __syncthreads();
    int i = b * SCAN_B + threadIdx.x;
    if (i < NN) {
        g_rowptr[i] += s_off;
        g_dinv[i] = rsqrtf((float)(g_counts[i] + 1));   // +1 = self loop
    }
    if (i == 0) g_rowptr[NN] = NE;
}

__global__ void k_fill(const void* __restrict__ ei) {
    int i = blockIdx.x * blockDim.x + threadIdx.x;
    if (i >= NE) return;
    int is64 = g_is64;
    int s = load_idx(ei, (long long)i, is64);
    int d = load_idx(ei, (long long)NE + i, is64);
    int pos = g_rowptr[d] + atomicAdd(&g_fill[d], 1);
    g_col[pos] = s;
}

// ---------------- GEMM (tf32): g_msg[r] = fp16( (src[r] @ W) * dinv[r] ) ----------------
// src: external fp32 x (srcSel==0) or fp16 g_act.
__global__ void __launch_bounds__(256) k_gemm(const float* __restrict__ xext,
                                              int srcSel,
                                              const float* __restrict__ W) {
    __shared__ float sm[SMEM_FLOATS];
    float* As = sm;               // 64 x LDA
    float* Ws = sm + BM * LDA;    // 32 x LDW

    const bool useX = (srcSel == 0);
    int tid = threadIdx.x;
    int wid = tid >> 5;
    int stripe = wid >> 1;        // 0..3 (16-row stripe)
    int half   = wid & 1;         // 0..1 (64-col half)
    int rowBase = blockIdx.x * BM;

    wmma::fragment<wmma::accumulator, 16, 16, 8, float> acc[4];
    #pragma unroll
    for (int c = 0; c < 4; c++) wmma::fill_fragment(acc[c], 0.0f);

    for (int kc = 0; kc < 4; kc++) {              // K chunks of 32
        #pragma unroll
        for (int t = 0; t < 2; t++) {
            int idx = tid + t * 256;
            int r   = idx >> 3;
            int kq  = idx & 7;
            int grow = rowBase + r;
            float4 v = make_float4(0.f, 0.f, 0.f, 0.f);
            if (grow < NN) {
                if (useX) {
                    v = *(const float4*)&xext[(long long)grow * FF + kc * 32 + kq * 4];
                } else {
                    uint2 u = g_act[grow * MQ + kc * 8 + kq];
                    float2 lo = __half22float2(u2h(u.x));
                    float2 hi = __half22float2(u2h(u.y));
                    v = make_float4(lo.x, lo.y, hi.x, hi.y);
                }
            }
            float* dst = &As[r * LDA + kq * 4];
            dst[0] = wmma::__float_to_tf32(v.x);
            dst[1] = wmma::__float_to_tf32(v.y);
            dst[2] = wmma::__float_to_tf32(v.z);
            dst[3] = wmma::__float_to_tf32(v.w);
        }
        #pragma unroll
        for (int t = 0; t < 4; t++) {
            int idx = tid + t * 256;
            int k   = idx >> 5;
            int cq  = idx & 31;
            float4 v = *(const float4*)&W[(kc * 32 + k) * FF + cq * 4];
            float* dst = &Ws[k * LDW + cq * 4];
            dst[0] = wmma::__float_to_tf32(v.x);
            dst[1] = wmma::__float_to_tf32(v.y);
            dst[2] = wmma::__float_to_tf32(v.z);
            dst[3] = wmma::__float_to_tf32(v.w);
        }
        __syncthreads();

        #pragma unroll
        for (int kk = 0; kk < 4; kk++) {
            wmma::fragment<wmma::matrix_a, 16, 16, 8, wmma::precision::tf32, wmma::row_major> a;
            wmma::load_matrix_sync(a, &As[stripe * 16 * LDA + kk * 8], LDA);
            #pragma unroll
            for (int c = 0; c < 4; c++) {
                wmma::fragment<wmma::matrix_b, 16, 16, 8, wmma::precision::tf32, wmma::row_major> b;
                wmma::load_matrix_sync(b, &Ws[kk * 8 * LDW + half * 64 + c * 16], LDW);
                wmma::mma_sync(acc[c], a, b, acc[c]);
            }
        }
        __syncthreads();
    }

    // epilogue: frags -> shared -> dinv scale -> fp16 -> global
    float* Cs = sm;               // 64 x LDW
    #pragma unroll
    for (int c = 0; c < 4; c++)
        wmma::store_matrix_sync(&Cs[(stripe * 16) * LDW + half * 64 + c * 16],
                                acc[c], LDW, wmma::mem_row_major);
    __syncthreads();

    #pragma unroll
    for (int t = 0; t < 8; t++) {
        int idx = tid + t * 256;          // 64 rows x 32 quads
        int r = idx >> 5;
        int q = idx & 31;
        int grow = rowBase + r;
        if (grow < NN) {
            float dv = g_dinv[grow];
            float4 v = *(float4*)&Cs[r * LDW + q * 4];
            __half2 h0 = __floats2half2_rn(v.x * dv, v.y * dv);
            __half2 h1 = __floats2half2_rn(v.z * dv, v.w * dv);
            uint2 u;
            u.x = h2u(h0);
            u.y = h2u(h1);
            g_msg[grow * MQ + q] = u;
        }
    }
}

// ---------------- aggregation: act[v] = fp16( relu?( dinv[v]*sum msg + b ) ) ----
// shuffle-prefetch; 8 independent gathers in flight, 4 acc chains.
__device__ __forceinline__ void acc_msg(float4& a, uint2 m) {
    float2 lo = __half22float2(u2h(m.x));
    float2 hi = __half22float2(u2h(m.y));
    a.x += lo.x; a.y += lo.y; a.z += hi.x; a.w += hi.y;
}

__global__ void __launch_bounds__(256) k_agg(const float* __restrict__ bias,
                                             int do_relu) {
    int v    = (blockIdx.x * blockDim.x + threadIdx.x) >> 5;  // one warp per node
    int lane = threadIdx.x & 31;
    if (v >= NN) return;

    float4 a0 = make_float4(0.f, 0.f, 0.f, 0.f);
    float4 a1 = make_float4(0.f, 0.f, 0.f, 0.f);
    float4 a2 = make_float4(0.f, 0.f, 0.f, 0.f);
    float4 a3 = make_float4(0.f, 0.f, 0.f, 0.f);
    acc_msg(a0, g_msg[v * MQ + lane]);                        // self loop

    int s = g_rowptr[v];
    int deg = g_rowptr[v + 1] - s;

    for (int base = 0; base < deg; base += 32) {
        int rem = deg - base;
        int n = rem < 32 ? rem : 32;
        int myc = 0;
        if (lane < n) myc = g_col[s + base + lane];            // coalesced prefetch

        int jj = 0;
        for (; jj + 8 <= n; jj += 8) {
            int u0 = __shfl_sync(0xffffffffu, myc, jj);
            int u1 = __shfl_sync(0xffffffffu, myc, jj + 1);
            int u2 = __shfl_sync(0xffffffffu, myc, jj + 2);
            int u3 = __shfl_sync(0xffffffffu, myc, jj + 3);
            int u4 = __shfl_sync(0xffffffffu, myc, jj + 4);
            int u5 = __shfl_sync(0xffffffffu, myc, jj + 5);
            int u6 = __shfl_sync(0xffffffffu, myc, jj + 6);
            int u7 = __shfl_sync(0xffffffffu, myc, jj + 7);
            uint2 m0 = g_msg[u0 * MQ + lane];
            uint2 m1 = g_msg[u1 * MQ + lane];
            uint2 m2 = g_msg[u2 * MQ + lane];
            uint2 m3 = g_msg[u3 * MQ + lane];
            uint2 m4 = g_msg[u4 * MQ + lane];
            uint2 m5 = g_msg[u5 * MQ + lane];
            uint2 m6 = g_msg[u6 * MQ + lane];
            uint2 m7 = g_msg[u7 * MQ + lane];
            acc_msg(a0, m0); acc_msg(a1, m1); acc_msg(a2, m2); acc_msg(a3, m3);
            acc_msg(a0, m4); acc_msg(a1, m5); acc_msg(a2, m6); acc_msg(a3, m7);
        }
        for (; jj + 2 <= n; jj += 2) {
            int u0 = __shfl_sync(0xffffffffu, myc, jj);
            int u1 = __shfl_sync(0xffffffffu, myc, jj + 1);
            uint2 m0 = g_msg[u0 * MQ + lane];
            uint2 m1 = g_msg[u1 * MQ + lane];
            acc_msg(a0, m0); acc_msg(a1, m1);
        }
        if (jj < n) {
            int u = __shfl_sync(0xffffffffu, myc, jj);
            acc_msg(a2, g_msg[u * MQ + lane]);
        }
    }

    float  dv = g_dinv[v];
    float4 b  = *(const float4*)&bias[lane * 4];
    float4 acc;
    acc.x = (a0.x + a1.x + a2.x + a3.x) * dv + b.x;
    acc.y = (a0.y + a1.y + a2.y + a3.y) * dv + b.y;
    acc.z = (a0.z + a1.z + a2.z + a3.z) * dv + b.z;
    acc.w = (a0.w + a1.w + a2.w + a3.w) * dv + b.w;
    if (do_relu) {
        acc.x = fmaxf(acc.x, 0.f); acc.y = fmaxf(acc.y, 0.f);
        acc.z = fmaxf(acc.z, 0.f); acc.w = fmaxf(acc.w, 0.f);
    }
    __half2 h0 = __floats2half2_rn(acc.x, acc.y);
    __half2 h1 = __floats2half2_rn(acc.z, acc.w);
    uint2 u;
    u.x = h2u(h0);
    u.y = h2u(h1);
    g_act[v * MQ + lane] = u;
}

// ---------------- mean pooling per graph (batch sorted); reads fp16 g_act ----------------
__device__ __forceinline__ int lower_bound_idx(const void* a, int val, int is64) {
    int lo = 0, hi = NN;
    while (lo < hi) {
        int mid = (lo + hi) >> 1;
        if (load_idx(a, mid, is64) < val) lo = mid + 1; else hi = mid;
    }
    return lo;
}

__global__ void __launch_bounds__(1024) k_pool(const void* __restrict__ batch) {
    __shared__ int se[2];
    __shared__ float red[8][FF];
    int g = blockIdx.x;
    if (threadIdx.x == 0) {
        int is64 = g_is64;
        se[0] = lower_bound_idx(batch, g, is64);
        se[1] = lower_bound_idx(batch, g + 1, is64);
    }
    __syncthreads();
    int s = se[0], e = se[1];
    int col = threadIdx.x & 127;       // feature
    int rc  = threadIdx.x >> 7;        // 0..7 row chunk
    const __half* h = (const __half*)g_act;
    float sum = 0.f;
    for (int i = s + rc; i < e; i += 8) sum += __half2float(h[i * FF + col]);
    red[rc][col] = sum;
    __syncthreads();
    if (rc == 0) {
        float t = 0.f;
        #pragma unroll
        for (int k = 0; k < 8; k++) t += red[k][col];
        float cnt = (float)(e - s);
        g_pool[g * FF + col] = t / fmaxf(cnt, 1.0f);
    }
}

// ---------------- classifier ----------------
__global__ void k_cls(const float* __restrict__ Wc,
                      const float* __restrict__ bc,
                      float* __restrict__ out) {
    int tid = threadIdx.x;             // 1024 threads
    int g = tid >> 4;
    int c = tid & 15;
    float sum = bc[c];
    #pragma unroll 8
    for (int k = 0; k < FF; k++)
        sum += g_pool[g * FF + k] * Wc[k * NC + c];
    out[g * NC + c] = sum;
}

// ---------------- launch ----------------
extern "C" void kernel_launch(void* const* d_in, const int* in_sizes, int n_in,
                              void* d_out, int out_size) {
    const float* x  = (const float*)d_in[0];
    const void*  ei = d_in[1];
    const void*  batch = d_in[2];
    const float* W0 = (const float*)d_in[3];
    const float* b0 = (const float*)d_in[4];
    const float* W1 = (const float*)d_in[5];
    const float* b1 = (const float*)d_in[6];
    const float* W2 = (const float*)d_in[7];
    const float* b2 = (const float*)d_in[8];
    const float* Wc = (const float*)d_in[9];
    const float* bc = (const float*)d_in[10];
    float* out = (float*)d_out;

    k_init <<<(NN + 255) / 256, 256>>>((const int*)ei);
    k_count<<<(NE + 255) / 256, 256>>>(ei);
    k_scan1<<<NBLK, SCAN_B>>>();
    k_scan3<<<NBLK, SCAN_B>>>();
    k_fill <<<(NE + 255) / 256, 256>>>(ei);

    const int gemm_grid = (NN + BM - 1) / BM;
    const int agg_grid  = (NN + 7) / 8;

    k_gemm<<<gemm_grid, 256>>>(x, 0, W0);
    k_agg <<<agg_grid,  256>>>(b0, 1);
    k_gemm<<<gemm_grid, 256>>>(x, 1, W1);
    k_agg <<<agg_grid,  256>>>(b1, 1);
    k_gemm<<<gemm_grid, 256>>>(x, 1, W2);
    k_agg <<<agg_grid,  256>>>(b2, 0);

    k_pool<<<NG, 1024>>>(batch);
    k_cls <<<1, 1024>>>(Wc, bc, out);
}

// round 9
// speedup vs baseline: 1.0610x; 1.0610x over previous
#include <cuda_runtime.h>
#include <cuda_fp16.h>
#include <mma.h>

using namespace nvcuda;

#define NN 50000
#define NE 800000
#define FF 128
#define MQ 32                      // uint2 (4 halves) per fp16 row
#define NG 64
#define NC 16
#define SCAN_B 512
#define NBLK ((NN + SCAN_B - 1) / SCAN_B)   // 98

// GEMM tiling
#define BM 128
#define LDA 40                     // 32 + 8 skew
#define LDW 136                    // 128 + 8 skew
#define SMEM_FLOATS (BM * LDA + 32 * LDW)   // 5120+4352=9472 floats (37.9KB); Cs reuse = 64*136=8704

// ---------------- scratch (static device globals; no allocation) ----------------
__device__ int    g_is64;
__device__ int    g_counts[NN];
__device__ int    g_fill[NN];
__device__ int    g_rowptr[NN + 1];
__device__ int    g_col[NE];
__device__ float  g_dinv[NN];
__device__ uint2  g_msg[NN * MQ];    // fp16 messages (dinv-scaled GEMM output)
__device__ uint2  g_act[NN * MQ];    // fp16 activations (agg output, layer input)
__device__ float  g_pool[NG * FF];
__device__ int    g_bsum[NBLK];

// bit reinterpretation helpers
__device__ __forceinline__ unsigned h2u(__half2 h) { return *reinterpret_cast<unsigned*>(&h); }
__device__ __forceinline__ __half2 u2h(unsigned u) { return *reinterpret_cast<__half2*>(&u); }

// dtype-agnostic index load (edge_index / batch may be int32 or int64)
__device__ __forceinline__ int load_idx(const void* p, long long i, int is64) {
    if (is64) return (int)((const long long*)p)[i];
    return ((const int*)p)[i];
}

// ---------------- init: zero counts + dtype detect ----------------
__global__ void k_init(const int* __restrict__ w32) {
    int i = blockIdx.x * blockDim.x + threadIdx.x;
    if (i < NN) { g_counts[i] = 0; g_fill[i] = 0; }
    if (i == 0) {
        int nz = 0;
        #pragma unroll
        for (int k = 0; k < 16; k++) nz |= w32[2 * k + 1];
        g_is64 = (nz == 0) ? 1 : 0;
    }
}

__global__ void k_count(const void* __restrict__ ei) {
    int i = blockIdx.x * blockDim.x + threadIdx.x;
    if (i >= NE) return;
    int d = load_idx(ei, (long long)NE + i, g_is64);
    atomicAdd(&g_counts[d], 1);
}

// block-wide inclusive scan via shuffles; writes exclusive partials + block sums
__global__ void k_scan1() {
    __shared__ int warp_sums[SCAN_B / 32];
    int i = blockIdx.x * SCAN_B + threadIdx.x;
    int v = (i < NN) ? g_counts[i] : 0;
    int lane = threadIdx.x & 31;
    int wid  = threadIdx.x >> 5;

    int x = v;
    #pragma unroll
    for (int off = 1; off < 32; off <<= 1) {
        int t = __shfl_up_sync(0xffffffffu, x, off);
        if (lane >= off) x += t;
    }
    if (lane == 31) warp_sums[wid] = x;
    __syncthreads();
    if (wid == 0) {
        int w = (lane < SCAN_B / 32) ? warp_sums[lane] : 0;
        #pragma unroll
        for (int off = 1; off < SCAN_B / 32; off <<= 1) {
            int t = __shfl_up_sync(0xffffffffu, w, off);
            if (lane >= off) w += t;
        }
        if (lane < SCAN_B / 32) warp_sums[lane] = w;
    }
    __syncthreads();
    int base = (wid > 0) ? warp_sums[wid - 1] : 0;
    int incl = base + x;
    if (i < NN) g_rowptr[i] = incl - v;            // exclusive within block
    if (threadIdx.x == SCAN_B - 1) g_bsum[blockIdx.x] = incl;
}

// finalize rowptr: block b adds sum(bsum[0..b-1]); also compute dinv
__global__ void k_scan3() {
    __shared__ int s_off;
    int b = blockIdx.x;
    if (threadIdx.x < 32) {
        int acc = 0;
        for (int k = threadIdx.x; k < b; k += 32) acc += g_bsum[k];
        #pragma unroll
        for (int off = 16; off; off >>= 1) acc += __shfl_down_sync(0xffffffffu, acc, off);
        if (threadIdx.x == 0) s_off = acc;
    }
    __syncthreads();
    int i = b * SCAN_B + threadIdx.x;
    if (i < NN) {
        g_rowptr[i] += s_off;
        g_dinv[i] = rsqrtf((float)(g_counts[i] + 1));   // +1 = self loop
    }
    if (i == 0) g_rowptr[NN] = NE;
}

__global__ void k_fill(const void* __restrict__ ei) {
    int i = blockIdx.x * blockDim.x + threadIdx.x;
    if (i >= NE) return;
    int is64 = g_is64;
    int s = load_idx(ei, (long long)i, is64);
    int d = load_idx(ei, (long long)NE + i, is64);
    int pos = g_rowptr[d] + atomicAdd(&g_fill[d], 1);
    g_col[pos] = s;
}

// ---------------- GEMM (tf32): g_msg[r] = fp16( (src[r] @ W) * dinv[r] ) ----------------
// BM=128 rows/block, 128 cols, 8 warps. Warp: 32 rows (2 frag rows) x 64 cols (4 frag cols).
__global__ void __launch_bounds__(256) k_gemm(const float* __restrict__ xext,
                                              int srcSel,
                                              const float* __restrict__ W) {
    __shared__ float sm[SMEM_FLOATS];
    float* As = sm;               // 128 x LDA
    float* Ws = sm + BM * LDA;    // 32 x LDW

    const bool useX = (srcSel == 0);
    int tid = threadIdx.x;
    int wid = tid >> 5;
    int stripe = wid >> 1;        // 0..3 -> rows [stripe*32, +32)
    int half   = wid & 1;         // 0..1 -> cols [half*64, +64)
    int rowBase = blockIdx.x * BM;

    wmma::fragment<wmma::accumulator, 16, 16, 8, float> acc[2][4];
    #pragma unroll
    for (int r = 0; r < 2; r++)
        #pragma unroll
        for (int c = 0; c < 4; c++) wmma::fill_fragment(acc[r][c], 0.0f);

    for (int kc = 0; kc < 4; kc++) {              // K chunks of 32
        // A tile: 128x32 floats = 1024 float4, 4 per thread
        #pragma unroll
        for (int t = 0; t < 4; t++) {
            int idx = tid + t * 256;
            int r   = idx >> 3;
            int kq  = idx & 7;
            int grow = rowBase + r;
            float4 v = make_float4(0.f, 0.f, 0.f, 0.f);
            if (grow < NN) {
                if (useX) {
                    v = *(const float4*)&xext[(long long)grow * FF + kc * 32 + kq * 4];
                } else {
                    uint2 u = g_act[grow * MQ + kc * 8 + kq];
                    float2 lo = __half22float2(u2h(u.x));
                    float2 hi = __half22float2(u2h(u.y));
                    v = make_float4(lo.x, lo.y, hi.x, hi.y);
                }
            }
            float* dst = &As[r * LDA + kq * 4];
            dst[0] = wmma::__float_to_tf32(v.x);
            dst[1] = wmma::__float_to_tf32(v.y);
            dst[2] = wmma::__float_to_tf32(v.z);
            dst[3] = wmma::__float_to_tf32(v.w);
        }
        // W chunk: 32x128 floats = 1024 float4, 4 per thread
        #pragma unroll
        for (int t = 0; t < 4; t++) {
            int idx = tid + t * 256;
            int k   = idx >> 5;
            int cq  = idx & 31;
            float4 v = *(const float4*)&W[(kc * 32 + k) * FF + cq * 4];
            float* dst = &Ws[k * LDW + cq * 4];
            dst[0] = wmma::__float_to_tf32(v.x);
            dst[1] = wmma::__float_to_tf32(v.y);
            dst[2] = wmma::__float_to_tf32(v.z);
            dst[3] = wmma::__float_to_tf32(v.w);
        }
        __syncthreads();

        #pragma unroll
        for (int kk = 0; kk < 4; kk++) {
            wmma::fragment<wmma::matrix_a, 16, 16, 8, wmma::precision::tf32, wmma::row_major> a0, a1;
            wmma::load_matrix_sync(a0, &As[(stripe * 32) * LDA + kk * 8], LDA);
            wmma::load_matrix_sync(a1, &As[(stripe * 32 + 16) * LDA + kk * 8], LDA);
            #pragma unroll
            for (int c = 0; c < 4; c++) {
                wmma::fragment<wmma::matrix_b, 16, 16, 8, wmma::precision::tf32, wmma::row_major> b;
                wmma::load_matrix_sync(b, &Ws[kk * 8 * LDW + half * 64 + c * 16], LDW);
                wmma::mma_sync(acc[0][c], a0, b, acc[0][c]);
                wmma::mma_sync(acc[1][c], a1, b, acc[1][c]);
            }
        }
        __syncthreads();
    }

    // epilogue in two 64-row passes through shared (Cs = 64 x LDW, reuses sm)
    float* Cs = sm;
    #pragma unroll
    for (int pass = 0; pass < 2; pass++) {
        if ((stripe >> 1) == pass) {
            int localStripe = stripe & 1;          // 0..1 within pass
            #pragma unroll
            for (int rt = 0; rt < 2; rt++)
                #pragma unroll
                for (int c = 0; c < 4; c++)
                    wmma::store_matrix_sync(&Cs[(localStripe * 32 + rt * 16) * LDW + half * 64 + c * 16],
                                            acc[rt][c], LDW, wmma::mem_row_major);
        }
        __syncthreads();
        #pragma unroll
        for (int t = 0; t < 8; t++) {
            int idx = tid + t * 256;               // 64 rows x 32 quads
            int r = idx >> 5;
            int q = idx & 31;
            int grow = rowBase + pass * 64 + r;
            if (grow < NN) {
                float dv = g_dinv[grow];
                float4 v = *(float4*)&Cs[r * LDW + q * 4];
                __half2 h0 = __floats2half2_rn(v.x * dv, v.y * dv);
                __half2 h1 = __floats2half2_rn(v.z * dv, v.w * dv);
                uint2 u;
                u.x = h2u(h0);
                u.y = h2u(h1);
                g_msg[grow * MQ + q] = u;
            }
        }
        __syncthreads();
    }
}

// ---------------- aggregation: act[v] = fp16( relu?( dinv[v]*sum msg + b ) ) ----
// shuffle-prefetch; 8 gathers in flight; half2 accumulation (4 chains).
__global__ void __launch_bounds__(256) k_agg(const float* __restrict__ bias,
                                             int do_relu) {
    int v    = (blockIdx.x * blockDim.x + threadIdx.x) >> 5;  // one warp per node
    int lane = threadIdx.x & 31;
    if (v >= NN) return;

    // self loop seeds chain 0
    uint2 mself = g_msg[(v << 5) + lane];
    __half2 c0a = u2h(mself.x), c0b = u2h(mself.y);
    __half2 z = __floats2half2_rn(0.f, 0.f);
    __half2 c1a = z, c1b = z, c2a = z, c2b = z, c3a = z, c3b = z;

    int s = g_rowptr[v];
    int deg = g_rowptr[v + 1] - s;

    for (int base = 0; base < deg; base += 32) {
        int rem = deg - base;
        int n = rem < 32 ? rem : 32;
        int myc = 0;
        if (lane < n) myc = g_col[s + base + lane];            // coalesced prefetch

        int jj = 0;
        for (; jj + 8 <= n; jj += 8) {
            int u0 = __shfl_sync(0xffffffffu, myc, jj);
            int u1 = __shfl_sync(0xffffffffu, myc, jj + 1);
            int u2 = __shfl_sync(0xffffffffu, myc, jj + 2);
            int u3 = __shfl_sync(0xffffffffu, myc, jj + 3);
            int u4 = __shfl_sync(0xffffffffu, myc, jj + 4);
            int u5 = __shfl_sync(0xffffffffu, myc, jj + 5);
            int u6 = __shfl_sync(0xffffffffu, myc, jj + 6);
            int u7 = __shfl_sync(0xffffffffu, myc, jj + 7);
            uint2 m0 = g_msg[(u0 << 5) + lane];
            uint2 m1 = g_msg[(u1 << 5) + lane];
            uint2 m2 = g_msg[(u2 << 5) + lane];
            uint2 m3 = g_msg[(u3 << 5) + lane];
            uint2 m4 = g_msg[(u4 << 5) + lane];
            uint2 m5 = g_msg[(u5 << 5) + lane];
            uint2 m6 = g_msg[(u6 << 5) + lane];
            uint2 m7 = g_msg[(u7 << 5) + lane];
            c0a = __hadd2(c0a, u2h(m0.x)); c0b = __hadd2(c0b, u2h(m0.y));
            c1a = __hadd2(c1a, u2h(m1.x)); c1b = __hadd2(c1b, u2h(m1.y));
            c2a = __hadd2(c2a, u2h(m2.x)); c2b = __hadd2(c2b, u2h(m2.y));
            c3a = __hadd2(c3a, u2h(m3.x)); c3b = __hadd2(c3b, u2h(m3.y));
            c0a = __hadd2(c0a, u2h(m4.x)); c0b = __hadd2(c0b, u2h(m4.y));
            c1a = __hadd2(c1a, u2h(m5.x)); c1b = __hadd2(c1b, u2h(m5.y));
            c2a = __hadd2(c2a, u2h(m6.x)); c2b = __hadd2(c2b, u2h(m6.y));
            c3a = __hadd2(c3a, u2h(m7.x)); c3b = __hadd2(c3b, u2h(m7.y));
        }
        for (; jj + 2 <= n; jj += 2) {
            int u0 = __shfl_sync(0xffffffffu, myc, jj);
            int u1 = __shfl_sync(0xffffffffu, myc, jj + 1);
            uint2 m0 = g_msg[(u0 << 5) + lane];
            uint2 m1 = g_msg[(u1 << 5) + lane];
            c0a = __hadd2(c0a, u2h(m0.x)); c0b = __hadd2(c0b, u2h(m0.y));
            c1a = __hadd2(c1a, u2h(m1.x)); c1b = __hadd2(c1b, u2h(m1.y));
        }
        if (jj < n) {
            int u = __shfl_sync(0xffffffffu, myc, jj);
            uint2 m = g_msg[(u << 5) + lane];
            c2a = __hadd2(c2a, u2h(m.x)); c2b = __hadd2(c2b, u2h(m.y));
        }
    }

    // combine chains in fp32
    float2 f0a = __half22float2(c0a), f1a = __half22float2(c1a);
    float2 f2a = __half22float2(c2a), f3a = __half22float2(c3a);
    float2 f0b = __half22float2(c0b), f1b = __half22float2(c1b);
    float2 f2b = __half22float2(c2b), f3b = __half22float2(c3b);

    float  dv = g_dinv[v];
    float4 b  = *(const float4*)&bias[lane * 4];
    float4 acc;
    acc.x = (f0a.x + f1a.x + f2a.x + f3a.x) * dv + b.x;
    acc.y = (f0a.y + f1a.y + f2a.y + f3a.y) * dv + b.y;
    acc.z = (f0b.x + f1b.x + f2b.x + f3b.x) * dv + b.z;
    acc.w = (f0b.y + f1b.y + f2b.y + f3b.y) * dv + b.w;
    if (do_relu) {
        acc.x = fmaxf(acc.x, 0.f); acc.y = fmaxf(acc.y, 0.f);
        acc.z = fmaxf(acc.z, 0.f); acc.w = fmaxf(acc.w, 0.f);
    }
    __half2 h0 = __floats2half2_rn(acc.x, acc.y);
    __half2 h1 = __floats2half2_rn(acc.z, acc.w);
    uint2 u;
    u.x = h2u(h0);
    u.y = h2u(h1);
    g_act[(v << 5) + lane] = u;
}

// ---------------- mean pooling per graph (batch sorted); reads fp16 g_act ----------------
__device__ __forceinline__ int lower_bound_idx(const void* a, int val, int is64) {
    int lo = 0, hi = NN;
    while (lo < hi) {
        int mid = (lo + hi) >> 1;
        if (load_idx(a, mid, is64) < val) lo = mid + 1; else hi = mid;
    }
    return lo;
}

__global__ void __launch_bounds__(1024) k_pool(const void* __restrict__ batch) {
    __shared__ int se[2];
    __shared__ float red[8][FF];
    int g = blockIdx.x;
    if (threadIdx.x == 0) {
        int is64 = g_is64;
        se[0] = lower_bound_idx(batch, g, is64);
        se[1] = lower_bound_idx(batch, g + 1, is64);
    }
    __syncthreads();
    int s = se[0], e = se[1];
    int col = threadIdx.x & 127;       // feature
    int rc  = threadIdx.x >> 7;        // 0..7 row chunk
    const __half* h = (const __half*)g_act;
    float sum = 0.f;
    for (int i = s + rc; i < e; i += 8) sum += __half2float(h[i * FF + col]);
    red[rc][col] = sum;
    __syncthreads();
    if (rc == 0) {
        float t = 0.f;
        #pragma unroll
        for (int k = 0; k < 8; k++) t += red[k][col];
        float cnt = (float)(e - s);
        g_pool[g * FF + col] = t / fmaxf(cnt, 1.0f);
    }
}

// ---------------- classifier ----------------
__global__ void k_cls(const float* __restrict__ Wc,
                      const float* __restrict__ bc,
                      float* __restrict__ out) {
    int tid = threadIdx.x;             // 1024 threads
    int g = tid >> 4;
    int c = tid & 15;
    float sum = bc[c];
    #pragma unroll 8
    for (int k = 0; k < FF; k++)
        sum += g_pool[g * FF + k] * Wc[k * NC + c];
    out[g * NC + c] = sum;
}

// ---------------- launch ----------------
extern "C" void kernel_launch(void* const* d_in, const int* in_sizes, int n_in,
                              void* d_out, int out_size) {
    const float* x  = (const float*)d_in[0];
    const void*  ei = d_in[1];
    const void*  batch = d_in[2];
    const float* W0 = (const float*)d_in[3];
    const float* b0 = (const float*)d_in[4];
    const float* W1 = (const float*)d_in[5];
    const float* b1 = (const float*)d_in[6];
    const float* W2 = (const float*)d_in[7];
    const float* b2 = (const float*)d_in[8];
    const float* Wc = (const float*)d_in[9];
    const float* bc = (const float*)d_in[10];
    float* out = (float*)d_out;

    k_init <<<(NN + 255) / 256, 256>>>((const int*)ei);
    k_count<<<(NE + 255) / 256, 256>>>(ei);
    k_scan1<<<NBLK, SCAN_B>>>();
    k_scan3<<<NBLK, SCAN_B>>>();
    k_fill <<<(NE + 255) / 256, 256>>>(ei);

    const int gemm_grid = (NN + BM - 1) / BM;
    const int agg_grid  = (NN + 7) / 8;

    k_gemm<<<gemm_grid, 256>>>(x, 0, W0);
    k_agg <<<agg_grid,  256>>>(b0, 1);
    k_gemm<<<gemm_grid, 256>>>(x, 1, W1);
    k_agg <<<agg_grid,  256>>>(b1, 1);
    k_gemm<<<gemm_grid, 256>>>(x, 1, W2);
    k_agg <<<agg_grid,  256>>>(b2, 0);

    k_pool<<<NG, 1024>>>(batch);
    k_cls <<<1, 1024>>>(Wc, bc, out);
}